// round 10
// baseline (speedup 1.0000x reference)
#include <cuda_runtime.h>
#include <cuda_fp16.h>
#include <cstdint>
#include <cstddef>

#define NN     50000
#define HID    64
#define EMAX   800000
#define IN_DIM 512
#define SCAN_B 256

// ---------------------------------------------------------------------------
// Scratch (__device__ globals; no allocation allowed)
// ---------------------------------------------------------------------------
__device__ __align__(256) float g_dinv[NN];
__device__ int   g_cnt[NN];
__device__ int   g_rowptr[NN + 1];
__device__ int   g_cursor[NN];
__device__ int   g_col[EMAX];
__device__ int   g_bsum[(NN + SCAN_B - 1) / SCAN_B];
__device__ int   g_boff[(NN + SCAN_B - 1) / SCAN_B];
__device__ __align__(256) __half g_h[NN * HID];     // GEMM outputs (fp16)
__device__ __align__(256) float  g_agg[NN * HID];   // agg1 output (fp32, GEMM2 input)

// ---------------------------------------------------------------------------
// CSR build
// ---------------------------------------------------------------------------
__global__ void k_zero(int* cnt, int n) {
    int i = blockIdx.x * blockDim.x + threadIdx.x;
    if (i < n) cnt[i] = 0;
}

__global__ void k_count(const int* __restrict__ dst, int* cnt, int E) {
    int stride = gridDim.x * blockDim.x;
    for (int e = blockIdx.x * blockDim.x + threadIdx.x; e < E; e += stride)
        atomicAdd(&cnt[dst[e]], 1);
}

// S1: per-block sums of cnt (coalesced)
__global__ void __launch_bounds__(SCAN_B)
k_s1(const int* __restrict__ cnt, int* bsum, int n) {
    int i = blockIdx.x * SCAN_B + threadIdx.x;
    int v = (i < n) ? cnt[i] : 0;
#pragma unroll
    for (int d = 16; d > 0; d >>= 1) v += __shfl_down_sync(0xffffffffu, v, d);
    __shared__ int ws[8];
    int lane = threadIdx.x & 31, wid = threadIdx.x >> 5;
    if (lane == 0) ws[wid] = v;
    __syncthreads();
    if (wid == 0) {
        int s = (lane < 8) ? ws[lane] : 0;
#pragma unroll
        for (int d = 4; d > 0; d >>= 1) s += __shfl_down_sync(0xffffffffu, s, d);
        if (lane == 0) bsum[blockIdx.x] = s;
    }
}

// S2: single block scans per-block sums -> offsets; writes rowptr[n]
__global__ void __launch_bounds__(SCAN_B)
k_s2(const int* __restrict__ bsum, int* boff, int* rowptr, int nb, int n) {
    int t = threadIdx.x;
    int v = (t < nb) ? bsum[t] : 0;
    int lane = t & 31, wid = t >> 5;
    int inc = v;
#pragma unroll
    for (int d = 1; d < 32; d <<= 1) {
        int u = __shfl_up_sync(0xffffffffu, inc, d);
        if (lane >= d) inc += u;
    }
    __shared__ int ws[8];
    if (lane == 31) ws[wid] = inc;
    __syncthreads();
    if (wid == 0 && lane < 8) {
        int w = ws[lane];
#pragma unroll
        for (int d = 1; d < 8; d <<= 1) {
            int u = __shfl_up_sync(0xffu, w, d);
            if (lane >= d) w += u;
        }
        ws[lane] = w;
    }
    __syncthreads();
    int incl = inc + (wid > 0 ? ws[wid - 1] : 0);
    int excl = incl - v;
    if (t < nb) boff[t] = excl;
    if (t == nb - 1) rowptr[n] = incl;
}

// S3: block-local exclusive scan + offset; writes rowptr/cursor/dinv (coalesced)
__global__ void __launch_bounds__(SCAN_B)
k_s3(const int* __restrict__ cnt, const int* __restrict__ boff,
     int* rowptr, int* cursor, float* dinv, int n) {
    int t = threadIdx.x;
    int i = blockIdx.x * SCAN_B + t;
    int c = (i < n) ? cnt[i] : 0;
    int lane = t & 31, wid = t >> 5;
    int inc = c;
#pragma unroll
    for (int d = 1; d < 32; d <<= 1) {
        int u = __shfl_up_sync(0xffffffffu, inc, d);
        if (lane >= d) inc += u;
    }
    __shared__ int ws[8];
    if (lane == 31) ws[wid] = inc;
    __syncthreads();
    if (wid == 0 && lane < 8) {
        int w = ws[lane];
#pragma unroll
        for (int d = 1; d < 8; d <<= 1) {
            int u = __shfl_up_sync(0xffu, w, d);
            if (lane >= d) w += u;
        }
        ws[lane] = w;
    }
    __syncthreads();
    int excl = inc - c + (wid > 0 ? ws[wid - 1] : 0) + boff[blockIdx.x];
    if (i < n) {
        rowptr[i] = excl;
        cursor[i] = excl;
        dinv[i]   = rsqrtf((float)(c + 1));
    }
}

__global__ void k_fill(const int* __restrict__ src, const int* __restrict__ dst,
                       int* cursor, int* col, int E) {
    int stride = gridDim.x * blockDim.x;
    for (int e = blockIdx.x * blockDim.x + threadIdx.x; e < E; e += stride) {
        int d = dst[e];
        int pos = atomicAdd(&cursor[d], 1);
        col[pos] = src[e];
    }
}

// ---------------------------------------------------------------------------
// tf32 tensor-core GEMM, cp.async 3-stage pipeline, BK=16, static smem 43.5KB.
//   h = X @ W (unscaled), OUTPUT IN FP16.
// BM=128, BN=64(full). 256 threads = 8 warps (4M x 2N), warp tile 32x32.
// ---------------------------------------------------------------------------
#define BM 128
#define BKG 16
#define PA 20
#define PB 72
#define NSTAGE 3

__device__ __forceinline__ uint32_t cvt_tf32(float x) {
    uint32_t r;
    asm("cvt.rna.tf32.f32 %0, %1;" : "=r"(r) : "f"(x));
    return r;
}

template <int K>
__global__ void __launch_bounds__(256)
k_gemm(const float* __restrict__ X, const float* __restrict__ W,
       __half* __restrict__ h, int M) {
    __shared__ float as[NSTAGE * BM * PA];
    __shared__ float ws[NSTAGE * BKG * PB];

    const int t    = threadIdx.x;
    const int m0   = blockIdx.x * BM;
    const int lane = t & 31;
    const int wid  = t >> 5;
    const int wm   = wid >> 1;
    const int wn   = wid & 1;
    const int g    = lane >> 2;
    const int tig  = lane & 3;

    float c[2][4][4];
#pragma unroll
    for (int mt = 0; mt < 2; mt++)
#pragma unroll
        for (int nt = 0; nt < 4; nt++)
#pragma unroll
            for (int i = 0; i < 4; i++) c[mt][nt][i] = 0.0f;

    auto load_stage = [&](int buf, int k0) {
        float* asb = as + buf * BM * PA;
        float* wsb = ws + buf * BKG * PB;
#pragma unroll
        for (int i = 0; i < 2; i++) {
            int G = i * 256 + t;
            int row = G >> 2, gg = G & 3;
            bool ok = (m0 + row) < M;
            const float* gp = ok ? (X + (size_t)(m0 + row) * K + k0 + gg * 4) : X;
            uint32_t sa = (uint32_t)__cvta_generic_to_shared(asb + row * PA + gg * 4);
            int sz = ok ? 16 : 0;
            asm volatile("cp.async.cg.shared.global [%0], [%1], 16, %2;\n"
                         :: "r"(sa), "l"(gp), "r"(sz));
        }
        {
            int kr = t >> 4, gn = t & 15;
            const float* gp = W + (size_t)(k0 + kr) * 64 + gn * 4;
            uint32_t sa = (uint32_t)__cvta_generic_to_shared(wsb + kr * PB + gn * 4);
            asm volatile("cp.async.cg.shared.global [%0], [%1], 16;\n"
                         :: "r"(sa), "l"(gp));
        }
    };

    const int NIT = K / BKG;
    // prime stages 0 and 1
    load_stage(0, 0);
    asm volatile("cp.async.commit_group;\n");
    if (NIT > 1) load_stage(1, BKG);
    asm volatile("cp.async.commit_group;\n");

    for (int it = 0; it < NIT; it++) {
        if (it + 2 < NIT) load_stage((it + 2) % NSTAGE, (it + 2) * BKG);
        asm volatile("cp.async.commit_group;\n");
        asm volatile("cp.async.wait_group 2;\n");
        __syncthreads();

        const float* asb = as + (it % NSTAGE) * BM * PA;
        const float* wsb = ws + (it % NSTAGE) * BKG * PB;

#pragma unroll
        for (int ks = 0; ks < BKG; ks += 8) {
            uint32_t a[2][4], b[4][2];
#pragma unroll
            for (int mt = 0; mt < 2; mt++) {
                int r = wm * 32 + mt * 16 + g;
                a[mt][0] = cvt_tf32(asb[r * PA + ks + tig]);
                a[mt][1] = cvt_tf32(asb[(r + 8) * PA + ks + tig]);
                a[mt][2] = cvt_tf32(asb[r * PA + ks + tig + 4]);
                a[mt][3] = cvt_tf32(asb[(r + 8) * PA + ks + tig + 4]);
            }
#pragma unroll
            for (int nt = 0; nt < 4; nt++) {
                int n = wn * 32 + nt * 8 + g;
                b[nt][0] = cvt_tf32(wsb[(ks + tig) * PB + n]);
                b[nt][1] = cvt_tf32(wsb[(ks + tig + 4) * PB + n]);
            }
#pragma unroll
            for (int mt = 0; mt < 2; mt++)
#pragma unroll
                for (int nt = 0; nt < 4; nt++) {
                    asm volatile(
                        "mma.sync.aligned.m16n8k8.row.col.f32.tf32.tf32.f32 "
                        "{%0,%1,%2,%3}, {%4,%5,%6,%7}, {%8,%9}, {%0,%1,%2,%3};"
                        : "+f"(c[mt][nt][0]), "+f"(c[mt][nt][1]),
                          "+f"(c[mt][nt][2]), "+f"(c[mt][nt][3])
                        : "r"(a[mt][0]), "r"(a[mt][1]), "r"(a[mt][2]), "r"(a[mt][3]),
                          "r"(b[nt][0]), "r"(b[nt][1]));
                }
        }
        __syncthreads();
    }

    // --- epilogue: h = acc (fp16)
#pragma unroll
    for (int mt = 0; mt < 2; mt++) {
        int rbase = m0 + wm * 32 + mt * 16 + g;
#pragma unroll
        for (int half = 0; half < 2; half++) {
            int row = rbase + half * 8;
            if (row < M) {
#pragma unroll
                for (int nt = 0; nt < 4; nt++) {
                    __half2 v = __floats2half2_rn(c[mt][nt][half * 2 + 0],
                                                  c[mt][nt][half * 2 + 1]);
                    *(__half2*)(h + (size_t)row * 64 + wn * 32 + nt * 8 + 2 * tig) = v;
                }
            }
        }
    }
}

// ---------------------------------------------------------------------------
// Fused aggregate (warp per node, fp16 h input, fp32 accumulate/output):
//   out[i] = act(dinv[i] * (h[i]*dinv[i] + sum_e h[col[e]]*dinv[col[e]]) + b)
// ---------------------------------------------------------------------------
template <bool RELU>
__global__ void __launch_bounds__(256)
k_agg(const int* __restrict__ rowptr, const int* __restrict__ col,
      const __half* __restrict__ h, const float* __restrict__ dinv,
      const float* __restrict__ bias, float* __restrict__ out, int n) {
    int w = (blockIdx.x * blockDim.x + threadIdx.x) >> 5;
    int lane = threadIdx.x & 31;
    if (w >= n) return;

    float di = __ldg(&dinv[w]);
    const __half* hrow = h + (size_t)w * 64;
    float a0 = __half2float(__ldg(&hrow[lane])) * di;
    float a1 = __half2float(__ldg(&hrow[lane + 32])) * di;

    int beg = __ldg(&rowptr[w]);
    int end = __ldg(&rowptr[w + 1]);

    for (int e0 = beg; e0 < end; e0 += 16) {
        int idx = e0 + (lane & 15);
        int cs = (idx < end) ? __ldg(&col[idx]) : -1;
#pragma unroll
        for (int j = 0; j < 16; j++) {
            int s = __shfl_sync(0xffffffffu, cs, j);
            if (s >= 0) {
                float ds = __ldg(&dinv[s]);
                const __half* hr = h + (size_t)s * 64;
                a0 = fmaf(__half2float(__ldg(&hr[lane])),      ds, a0);
                a1 = fmaf(__half2float(__ldg(&hr[lane + 32])), ds, a1);
            }
        }
    }

    float v0 = di * a0 + __ldg(&bias[lane]);
    float v1 = di * a1 + __ldg(&bias[lane + 32]);
    if (RELU) { v0 = fmaxf(v0, 0.0f); v1 = fmaxf(v1, 0.0f); }
    out[(size_t)w * 64 + lane]      = v0;
    out[(size_t)w * 64 + lane + 32] = v1;
}

// ---------------------------------------------------------------------------
// Launch
// ---------------------------------------------------------------------------
extern "C" void kernel_launch(void* const* d_in, const int* in_sizes, int n_in,
                              void* d_out, int out_size) {
    const float* x  = (const float*)d_in[0];
    const int*   ei = (const int*)d_in[1];
    const float* W1 = (const float*)d_in[2];
    const float* b1 = (const float*)d_in[3];
    const float* W2 = (const float*)d_in[4];
    const float* b2 = (const float*)d_in[5];

    const int E = in_sizes[1] / 2;
    const int M = out_size / HID;
    const int* src = ei;
    const int* dst = ei + E;

    float *dinv, *aggb;
    __half* hbuf;
    int *cnt, *rowptr, *cursor, *col, *bsum, *boff;
    cudaGetSymbolAddress((void**)&dinv,   g_dinv);
    cudaGetSymbolAddress((void**)&cnt,    g_cnt);
    cudaGetSymbolAddress((void**)&rowptr, g_rowptr);
    cudaGetSymbolAddress((void**)&cursor, g_cursor);
    cudaGetSymbolAddress((void**)&col,    g_col);
    cudaGetSymbolAddress((void**)&bsum,   g_bsum);
    cudaGetSymbolAddress((void**)&boff,   g_boff);
    cudaGetSymbolAddress((void**)&hbuf,   g_h);
    cudaGetSymbolAddress((void**)&aggb,   g_agg);
    float* out = (float*)d_out;

    const int gblk = (M + BM - 1) / BM;
    const int ablk = (M * 32 + 255) / 256;
    const int nb   = (M + SCAN_B - 1) / SCAN_B;

    // 1. CSR prefix (coalesced multi-block scan)
    k_zero<<<(M + 255) / 256, 256>>>(cnt, M);
    k_count<<<592, 256>>>(dst, cnt, E);
    k_s1<<<nb, SCAN_B>>>(cnt, bsum, M);
    // 2. GEMM1 at launch #4 (profiled): h1 = x@W1 -> hbuf (fp16)
    k_gemm<IN_DIM><<<gblk, 256>>>(x, W1, hbuf, M);
    k_s2<<<1, SCAN_B>>>(bsum, boff, rowptr, nb, M);
    k_s3<<<nb, SCAN_B>>>(cnt, boff, rowptr, cursor, dinv, M);
    k_fill<<<592, 256>>>(src, dst, cursor, col, E);

    // 3. agg1 (+bias1, ReLU) -> aggb (fp32)
    k_agg<true><<<ablk, 256>>>(rowptr, col, hbuf, dinv, b1, aggb, M);

    // 4. GEMM2: h2 = aggb@W2 -> hbuf (fp16) ; agg2 (+bias2) -> out (fp32)
    k_gemm<HID><<<gblk, 256>>>(aggb, W2, hbuf, M);
    k_agg<false><<<ablk, 256>>>(rowptr, col, hbuf, dinv, b2, out, M);
}

// round 11
// speedup vs baseline: 1.0604x; 1.0604x over previous
#include <cuda_runtime.h>
#include <cstdint>
#include <cstddef>

#define NN     50000
#define HID    64
#define EMAX   800000
#define IN_DIM 512
#define SCAN_B 256

// ---------------------------------------------------------------------------
// Scratch (__device__ globals; no allocation allowed)
// ---------------------------------------------------------------------------
__device__ __align__(256) float g_dinv[NN];
__device__ int   g_cnt[NN];
__device__ int   g_rowptr[NN + 1];
__device__ int   g_cursor[NN];
__device__ int   g_col[EMAX];
__device__ int   g_bsum[(NN + SCAN_B - 1) / SCAN_B];
__device__ __align__(256) float g_bufA[NN * HID];
__device__ __align__(256) float g_bufB[NN * HID];

// ---------------------------------------------------------------------------
// CSR build
// ---------------------------------------------------------------------------
__global__ void k_zero(int* cnt, int n) {
    int i = blockIdx.x * blockDim.x + threadIdx.x;
    if (i < n) cnt[i] = 0;
}

__global__ void k_count(const int* __restrict__ dst, int* cnt, int E) {
    int stride = gridDim.x * blockDim.x;
    for (int e = blockIdx.x * blockDim.x + threadIdx.x; e < E; e += stride)
        atomicAdd(&cnt[dst[e]], 1);
}

// S1: per-block sums of cnt (coalesced)
__global__ void __launch_bounds__(SCAN_B)
k_s1(const int* __restrict__ cnt, int* bsum, int n) {
    int i = blockIdx.x * SCAN_B + threadIdx.x;
    int v = (i < n) ? cnt[i] : 0;
#pragma unroll
    for (int d = 16; d > 0; d >>= 1) v += __shfl_down_sync(0xffffffffu, v, d);
    __shared__ int ws[8];
    int lane = threadIdx.x & 31, wid = threadIdx.x >> 5;
    if (lane == 0) ws[wid] = v;
    __syncthreads();
    if (wid == 0) {
        int s = (lane < 8) ? ws[lane] : 0;
#pragma unroll
        for (int d = 4; d > 0; d >>= 1) s += __shfl_down_sync(0xffffffffu, s, d);
        if (lane == 0) bsum[blockIdx.x] = s;
    }
}

// S3 (merged with S2): every block re-scans the nb block-sums locally (nb<=256),
// then does its block-local exclusive scan. Writes rowptr/cursor/dinv coalesced.
__global__ void __launch_bounds__(SCAN_B)
k_s3(const int* __restrict__ cnt, const int* __restrict__ bsum,
     int* rowptr, int* cursor, float* dinv, int nb, int n) {
    __shared__ int sb[SCAN_B];   // inclusive scan of bsum
    __shared__ int wsA[8], wsB[8];
    const int t = threadIdx.x;
    const int lane = t & 31, wid = t >> 5;

    // --- inclusive scan of bsum[0..nb) across the block
    int bv = (t < nb) ? bsum[t] : 0;
    int inc1 = bv;
#pragma unroll
    for (int d = 1; d < 32; d <<= 1) {
        int u = __shfl_up_sync(0xffffffffu, inc1, d);
        if (lane >= d) inc1 += u;
    }
    if (lane == 31) wsA[wid] = inc1;
    __syncthreads();
    if (wid == 0 && lane < 8) {
        int w = wsA[lane];
#pragma unroll
        for (int d = 1; d < 8; d <<= 1) {
            int u = __shfl_up_sync(0xffu, w, d);
            if (lane >= d) w += u;
        }
        wsA[lane] = w;
    }
    __syncthreads();
    sb[t] = inc1 + (wid > 0 ? wsA[wid - 1] : 0);
    __syncthreads();

    int base = (blockIdx.x > 0) ? sb[blockIdx.x - 1] : 0;
    if (blockIdx.x == 0 && t == 0) rowptr[n] = sb[nb - 1];

    // --- block-local exclusive scan of cnt
    int i = blockIdx.x * SCAN_B + t;
    int c = (i < n) ? cnt[i] : 0;
    int inc2 = c;
#pragma unroll
    for (int d = 1; d < 32; d <<= 1) {
        int u = __shfl_up_sync(0xffffffffu, inc2, d);
        if (lane >= d) inc2 += u;
    }
    if (lane == 31) wsB[wid] = inc2;
    __syncthreads();
    if (wid == 0 && lane < 8) {
        int w = wsB[lane];
#pragma unroll
        for (int d = 1; d < 8; d <<= 1) {
            int u = __shfl_up_sync(0xffu, w, d);
            if (lane >= d) w += u;
        }
        wsB[lane] = w;
    }
    __syncthreads();
    int excl = inc2 - c + (wid > 0 ? wsB[wid - 1] : 0) + base;
    if (i < n) {
        rowptr[i] = excl;
        cursor[i] = excl;
        dinv[i]   = rsqrtf((float)(c + 1));
    }
}

__global__ void k_fill(const int* __restrict__ src, const int* __restrict__ dst,
                       int* cursor, int* col, int E) {
    int stride = gridDim.x * blockDim.x;
    for (int e = blockIdx.x * blockDim.x + threadIdx.x; e < E; e += stride) {
        int d = dst[e];
        int pos = atomicAdd(&cursor[d], 1);
        col[pos] = src[e];
    }
}

// ---------------------------------------------------------------------------
// tf32 tensor-core GEMM, cp.async 2-stage, BM=64/BK=32, 128 threads (4 warps,
// 2x2 warp grid, warp tile 32x32). Grid = 782 -> ~5.3 blocks/SM.
//   h = X @ W (unscaled, fp32 out).
// ---------------------------------------------------------------------------
#define BM 64
#define BKG 32
#define PA 36
#define PB 72

__device__ __forceinline__ uint32_t cvt_tf32(float x) {
    uint32_t r;
    asm("cvt.rna.tf32.f32 %0, %1;" : "=r"(r) : "f"(x));
    return r;
}

template <int K>
__global__ void __launch_bounds__(128)
k_gemm(const float* __restrict__ X, const float* __restrict__ W,
       float* __restrict__ h, int M) {
    __shared__ float as[2 * BM * PA];   // 18.4 KB
    __shared__ float ws[2 * BKG * PB];  // 18.4 KB

    const int t    = threadIdx.x;       // 0..127
    const int m0   = blockIdx.x * BM;
    const int lane = t & 31;
    const int wid  = t >> 5;            // 0..3
    const int wm   = wid >> 1;          // 0..1
    const int wn   = wid & 1;           // 0..1
    const int g    = lane >> 2;
    const int tig  = lane & 3;

    float c[2][4][4];
#pragma unroll
    for (int mt = 0; mt < 2; mt++)
#pragma unroll
        for (int nt = 0; nt < 4; nt++)
#pragma unroll
            for (int i = 0; i < 4; i++) c[mt][nt][i] = 0.0f;

    // A tile 64x32 = 512 float4 (4/thread); B tile 32x64 = 512 float4 (4/thread)
    auto load_stage = [&](int buf, int k0) {
        float* asb = as + buf * BM * PA;
        float* wsb = ws + buf * BKG * PB;
#pragma unroll
        for (int i = 0; i < 4; i++) {
            int G = i * 128 + t;
            int row = G >> 3, gg = G & 7;
            bool ok = (m0 + row) < M;
            const float* gp = ok ? (X + (size_t)(m0 + row) * K + k0 + gg * 4) : X;
            uint32_t sa = (uint32_t)__cvta_generic_to_shared(asb + row * PA + gg * 4);
            int sz = ok ? 16 : 0;
            asm volatile("cp.async.cg.shared.global [%0], [%1], 16, %2;\n"
                         :: "r"(sa), "l"(gp), "r"(sz));
        }
#pragma unroll
        for (int i = 0; i < 4; i++) {
            int G = i * 128 + t;
            int kr = G >> 4, gn = G & 15;
            const float* gp = W + (size_t)(k0 + kr) * 64 + gn * 4;
            uint32_t sa = (uint32_t)__cvta_generic_to_shared(wsb + kr * PB + gn * 4);
            asm volatile("cp.async.cg.shared.global [%0], [%1], 16;\n"
                         :: "r"(sa), "l"(gp));
        }
    };

    load_stage(0, 0);
    asm volatile("cp.async.commit_group;\n");

    const int NIT = K / BKG;
    for (int it = 0; it < NIT; it++) {
        if (it + 1 < NIT) load_stage((it + 1) & 1, (it + 1) * BKG);
        asm volatile("cp.async.commit_group;\n");
        asm volatile("cp.async.wait_group 1;\n");
        __syncthreads();

        const float* asb = as + (it & 1) * BM * PA;
        const float* wsb = ws + (it & 1) * BKG * PB;

#pragma unroll
        for (int ks = 0; ks < BKG; ks += 8) {
            uint32_t a[2][4], b[4][2];
#pragma unroll
            for (int mt = 0; mt < 2; mt++) {
                int r = wm * 32 + mt * 16 + g;
                a[mt][0] = cvt_tf32(asb[r * PA + ks + tig]);
                a[mt][1] = cvt_tf32(asb[(r + 8) * PA + ks + tig]);
                a[mt][2] = cvt_tf32(asb[r * PA + ks + tig + 4]);
                a[mt][3] = cvt_tf32(asb[(r + 8) * PA + ks + tig + 4]);
            }
#pragma unroll
            for (int nt = 0; nt < 4; nt++) {
                int n = wn * 32 + nt * 8 + g;
                b[nt][0] = cvt_tf32(wsb[(ks + tig) * PB + n]);
                b[nt][1] = cvt_tf32(wsb[(ks + tig + 4) * PB + n]);
            }
#pragma unroll
            for (int mt = 0; mt < 2; mt++)
#pragma unroll
                for (int nt = 0; nt < 4; nt++) {
                    asm volatile(
                        "mma.sync.aligned.m16n8k8.row.col.f32.tf32.tf32.f32 "
                        "{%0,%1,%2,%3}, {%4,%5,%6,%7}, {%8,%9}, {%0,%1,%2,%3};"
                        : "+f"(c[mt][nt][0]), "+f"(c[mt][nt][1]),
                          "+f"(c[mt][nt][2]), "+f"(c[mt][nt][3])
                        : "r"(a[mt][0]), "r"(a[mt][1]), "r"(a[mt][2]), "r"(a[mt][3]),
                          "r"(b[nt][0]), "r"(b[nt][1]));
                }
        }
        __syncthreads();
    }

    // --- epilogue: h = acc (fp32, unscaled)
#pragma unroll
    for (int mt = 0; mt < 2; mt++) {
        int rbase = m0 + wm * 32 + mt * 16 + g;
#pragma unroll
        for (int half = 0; half < 2; half++) {
            int row = rbase + half * 8;
            if (row < M) {
#pragma unroll
                for (int nt = 0; nt < 4; nt++) {
                    float2 v;
                    v.x = c[mt][nt][half * 2 + 0];
                    v.y = c[mt][nt][half * 2 + 1];
                    *(float2*)(h + (size_t)row * 64 + wn * 32 + nt * 8 + 2 * tig) = v;
                }
            }
        }
    }
}

// ---------------------------------------------------------------------------
// Fused aggregate (warp per node, fp32 h — round-8 measured optimum):
//   out[i] = act(dinv[i] * (h[i]*dinv[i] + sum_e h[col[e]]*dinv[col[e]]) + b)
// ---------------------------------------------------------------------------
template <bool RELU>
__global__ void __launch_bounds__(256)
k_agg(const int* __restrict__ rowptr, const int* __restrict__ col,
      const float* __restrict__ h, const float* __restrict__ dinv,
      const float* __restrict__ bias, float* __restrict__ out, int n) {
    int w = (blockIdx.x * blockDim.x + threadIdx.x) >> 5;
    int lane = threadIdx.x & 31;
    if (w >= n) return;

    float di = __ldg(&dinv[w]);
    const float* hrow = h + (size_t)w * 64;
    float a0 = __ldg(&hrow[lane]) * di;
    float a1 = __ldg(&hrow[lane + 32]) * di;

    int beg = __ldg(&rowptr[w]);
    int end = __ldg(&rowptr[w + 1]);

    for (int e0 = beg; e0 < end; e0 += 16) {
        int idx = e0 + (lane & 15);
        int cs = (idx < end) ? __ldg(&col[idx]) : -1;
#pragma unroll
        for (int j = 0; j < 16; j++) {
            int s = __shfl_sync(0xffffffffu, cs, j);
            if (s >= 0) {
                float ds = __ldg(&dinv[s]);
                const float* hr = h + (size_t)s * 64;
                a0 = fmaf(__ldg(&hr[lane]),      ds, a0);
                a1 = fmaf(__ldg(&hr[lane + 32]), ds, a1);
            }
        }
    }

    float v0 = di * a0 + __ldg(&bias[lane]);
    float v1 = di * a1 + __ldg(&bias[lane + 32]);
    if (RELU) { v0 = fmaxf(v0, 0.0f); v1 = fmaxf(v1, 0.0f); }
    out[(size_t)w * 64 + lane]      = v0;
    out[(size_t)w * 64 + lane + 32] = v1;
}

// ---------------------------------------------------------------------------
// Launch (9 kernels; GEMM1 at slot #4 for profiling consistency)
// ---------------------------------------------------------------------------
extern "C" void kernel_launch(void* const* d_in, const int* in_sizes, int n_in,
                              void* d_out, int out_size) {
    const float* x  = (const float*)d_in[0];
    const int*   ei = (const int*)d_in[1];
    const float* W1 = (const float*)d_in[2];
    const float* b1 = (const float*)d_in[3];
    const float* W2 = (const float*)d_in[4];
    const float* b2 = (const float*)d_in[5];

    const int E = in_sizes[1] / 2;
    const int M = out_size / HID;
    const int* src = ei;
    const int* dst = ei + E;

    float *dinv, *bufA, *bufB;
    int *cnt, *rowptr, *cursor, *col, *bsum;
    cudaGetSymbolAddress((void**)&dinv,   g_dinv);
    cudaGetSymbolAddress((void**)&cnt,    g_cnt);
    cudaGetSymbolAddress((void**)&rowptr, g_rowptr);
    cudaGetSymbolAddress((void**)&cursor, g_cursor);
    cudaGetSymbolAddress((void**)&col,    g_col);
    cudaGetSymbolAddress((void**)&bsum,   g_bsum);
    cudaGetSymbolAddress((void**)&bufA,   g_bufA);
    cudaGetSymbolAddress((void**)&bufB,   g_bufB);
    float* out = (float*)d_out;

    const int gblk = (M + BM - 1) / BM;
    const int ablk = (M * 32 + 255) / 256;
    const int nb   = (M + SCAN_B - 1) / SCAN_B;

    // 1. CSR prefix
    k_zero<<<(M + 255) / 256, 256>>>(cnt, M);
    k_count<<<592, 256>>>(dst, cnt, E);
    k_s1<<<nb, SCAN_B>>>(cnt, bsum, M);
    // 2. GEMM1 at launch #4 (profiled): h1 = x@W1 -> bufA
    k_gemm<IN_DIM><<<gblk, 128>>>(x, W1, bufA, M);
    // 3. merged scan + fill
    k_s3<<<nb, SCAN_B>>>(cnt, bsum, rowptr, cursor, dinv, nb, M);
    k_fill<<<592, 256>>>(src, dst, cursor, col, E);

    // 4. agg1 (+bias1, ReLU) -> bufB
    k_agg<true><<<ablk, 256>>>(rowptr, col, bufA, dinv, b1, bufB, M);

    // 5. GEMM2 -> bufA ; agg2 (+bias2) -> out
    k_gemm<HID><<<gblk, 128>>>(bufB, W2, bufA, M);
    k_agg<false><<<ablk, 256>>>(rowptr, col, bufA, dinv, b2, out, M);
}

// round 12
// speedup vs baseline: 1.1176x; 1.0539x over previous
#include <cuda_runtime.h>
#include <cstdint>
#include <cstddef>

#define NN     50000
#define HID    64
#define EMAX   800000
#define IN_DIM 512
#define SCAN_B 256

// ---------------------------------------------------------------------------
// Scratch (__device__ globals; no allocation allowed)
// ---------------------------------------------------------------------------
__device__ __align__(256) float g_dinv[NN];
__device__ int   g_cnt[NN];
__device__ int   g_rowptr[NN + 1];
__device__ int   g_cursor[NN];
__device__ int   g_col[EMAX];
__device__ int   g_bsum[(NN + SCAN_B - 1) / SCAN_B];
__device__ __align__(256) float g_w1t[IN_DIM * HID];   // W1 as tf32 bits
__device__ __align__(256) float g_w2t[HID * HID];      // W2 as tf32 bits
__device__ __align__(256) float g_bufA[NN * HID];
__device__ __align__(256) float g_bufB[NN * HID];

__device__ __forceinline__ uint32_t cvt_tf32(float x) {
    uint32_t r;
    asm("cvt.rna.tf32.f32 %0, %1;" : "=r"(r) : "f"(x));
    return r;
}

// ---------------------------------------------------------------------------
// CSR build + prep
// ---------------------------------------------------------------------------
__global__ void k_zero(int* cnt, int n) {
    int i = blockIdx.x * blockDim.x + threadIdx.x;
    if (i < n) cnt[i] = 0;
}

__global__ void k_count(const int* __restrict__ dst, int* cnt, int E) {
    int stride = gridDim.x * blockDim.x;
    for (int e = blockIdx.x * blockDim.x + threadIdx.x; e < E; e += stride)
        atomicAdd(&cnt[dst[e]], 1);
}

// prep: dinv = rsqrt(deg+1); convert W1/W2 to tf32 bit patterns
__global__ void k_prep(const int* __restrict__ cnt, float* dinv,
                       const float* __restrict__ W1, const float* __restrict__ W2,
                       float* w1t, float* w2t, int n) {
    int i = blockIdx.x * blockDim.x + threadIdx.x;
    if (i < n) dinv[i] = rsqrtf((float)(cnt[i] + 1));
    if (i < IN_DIM * HID) w1t[i] = __uint_as_float(cvt_tf32(W1[i]));
    if (i < HID * HID)    w2t[i] = __uint_as_float(cvt_tf32(W2[i]));
}

// S1: per-block sums of cnt
__global__ void __launch_bounds__(SCAN_B)
k_s1(const int* __restrict__ cnt, int* bsum, int n) {
    int i = blockIdx.x * SCAN_B + threadIdx.x;
    int v = (i < n) ? cnt[i] : 0;
#pragma unroll
    for (int d = 16; d > 0; d >>= 1) v += __shfl_down_sync(0xffffffffu, v, d);
    __shared__ int ws[8];
    int lane = threadIdx.x & 31, wid = threadIdx.x >> 5;
    if (lane == 0) ws[wid] = v;
    __syncthreads();
    if (wid == 0) {
        int s = (lane < 8) ? ws[lane] : 0;
#pragma unroll
        for (int d = 4; d > 0; d >>= 1) s += __shfl_down_sync(0xffffffffu, s, d);
        if (lane == 0) bsum[blockIdx.x] = s;
    }
}

// S3: each block re-scans bsum locally then block-local exclusive scan of cnt.
__global__ void __launch_bounds__(SCAN_B)
k_s3(const int* __restrict__ cnt, const int* __restrict__ bsum,
     int* rowptr, int* cursor, int nb, int n) {
    __shared__ int sb[SCAN_B];
    __shared__ int wsA[8], wsB[8];
    const int t = threadIdx.x;
    const int lane = t & 31, wid = t >> 5;

    int bv = (t < nb) ? bsum[t] : 0;
    int inc1 = bv;
#pragma unroll
    for (int d = 1; d < 32; d <<= 1) {
        int u = __shfl_up_sync(0xffffffffu, inc1, d);
        if (lane >= d) inc1 += u;
    }
    if (lane == 31) wsA[wid] = inc1;
    __syncthreads();
    if (wid == 0 && lane < 8) {
        int w = wsA[lane];
#pragma unroll
        for (int d = 1; d < 8; d <<= 1) {
            int u = __shfl_up_sync(0xffu, w, d);
            if (lane >= d) w += u;
        }
        wsA[lane] = w;
    }
    __syncthreads();
    sb[t] = inc1 + (wid > 0 ? wsA[wid - 1] : 0);
    __syncthreads();

    int base = (blockIdx.x > 0) ? sb[blockIdx.x - 1] : 0;
    if (blockIdx.x == 0 && t == 0) rowptr[n] = sb[nb - 1];

    int i = blockIdx.x * SCAN_B + t;
    int c = (i < n) ? cnt[i] : 0;
    int inc2 = c;
#pragma unroll
    for (int d = 1; d < 32; d <<= 1) {
        int u = __shfl_up_sync(0xffffffffu, inc2, d);
        if (lane >= d) inc2 += u;
    }
    if (lane == 31) wsB[wid] = inc2;
    __syncthreads();
    if (wid == 0 && lane < 8) {
        int w = wsB[lane];
#pragma unroll
        for (int d = 1; d < 8; d <<= 1) {
            int u = __shfl_up_sync(0xffu, w, d);
            if (lane >= d) w += u;
        }
        wsB[lane] = w;
    }
    __syncthreads();
    int excl = inc2 - c + (wid > 0 ? wsB[wid - 1] : 0) + base;
    if (i < n) {
        rowptr[i] = excl;
        cursor[i] = excl;
    }
}

__global__ void k_fill(const int* __restrict__ src, const int* __restrict__ dst,
                       int* cursor, int* col, int E) {
    int stride = gridDim.x * blockDim.x;
    for (int e = blockIdx.x * blockDim.x + threadIdx.x; e < E; e += stride) {
        int d = dst[e];
        int pos = atomicAdd(&cursor[d], 1);
        col[pos] = src[e];
    }
}

// ---------------------------------------------------------------------------
// tf32 tensor-core GEMM, cp.async 2-stage, BM=64/BK=32, 128 threads.
//   hn = (X @ W) * dinv[row]   (pre-scaled output)
// W is PRE-CONVERTED to tf32 bits -> B fragments need no cvt.
// ---------------------------------------------------------------------------
#define BM 64
#define BKG 32
#define PA 36
#define PB 72

template <int K>
__global__ void __launch_bounds__(128)
k_gemm(const float* __restrict__ X, const float* __restrict__ Wt,
       const float* __restrict__ dinv, float* __restrict__ hn, int M) {
    __shared__ float as[2 * BM * PA];
    __shared__ float ws[2 * BKG * PB];

    const int t    = threadIdx.x;
    const int m0   = blockIdx.x * BM;
    const int lane = t & 31;
    const int wid  = t >> 5;
    const int wm   = wid >> 1;
    const int wn   = wid & 1;
    const int g    = lane >> 2;
    const int tig  = lane & 3;

    float c[2][4][4];
#pragma unroll
    for (int mt = 0; mt < 2; mt++)
#pragma unroll
        for (int nt = 0; nt < 4; nt++)
#pragma unroll
            for (int i = 0; i < 4; i++) c[mt][nt][i] = 0.0f;

    auto load_stage = [&](int buf, int k0) {
        float* asb = as + buf * BM * PA;
        float* wsb = ws + buf * BKG * PB;
#pragma unroll
        for (int i = 0; i < 4; i++) {
            int G = i * 128 + t;
            int row = G >> 3, gg = G & 7;
            bool ok = (m0 + row) < M;
            const float* gp = ok ? (X + (size_t)(m0 + row) * K + k0 + gg * 4) : X;
            uint32_t sa = (uint32_t)__cvta_generic_to_shared(asb + row * PA + gg * 4);
            int sz = ok ? 16 : 0;
            asm volatile("cp.async.cg.shared.global [%0], [%1], 16, %2;\n"
                         :: "r"(sa), "l"(gp), "r"(sz));
        }
#pragma unroll
        for (int i = 0; i < 4; i++) {
            int G = i * 128 + t;
            int kr = G >> 4, gn = G & 15;
            const float* gp = Wt + (size_t)(k0 + kr) * 64 + gn * 4;
            uint32_t sa = (uint32_t)__cvta_generic_to_shared(wsb + kr * PB + gn * 4);
            asm volatile("cp.async.cg.shared.global [%0], [%1], 16;\n"
                         :: "r"(sa), "l"(gp));
        }
    };

    load_stage(0, 0);
    asm volatile("cp.async.commit_group;\n");

    const int NIT = K / BKG;
    for (int it = 0; it < NIT; it++) {
        if (it + 1 < NIT) load_stage((it + 1) & 1, (it + 1) * BKG);
        asm volatile("cp.async.commit_group;\n");
        asm volatile("cp.async.wait_group 1;\n");
        __syncthreads();

        const float* asb = as + (it & 1) * BM * PA;
        const float* wsb = ws + (it & 1) * BKG * PB;

#pragma unroll
        for (int ks = 0; ks < BKG; ks += 8) {
            uint32_t a[2][4], b[4][2];
#pragma unroll
            for (int mt = 0; mt < 2; mt++) {
                int r = wm * 32 + mt * 16 + g;
                a[mt][0] = cvt_tf32(asb[r * PA + ks + tig]);
                a[mt][1] = cvt_tf32(asb[(r + 8) * PA + ks + tig]);
                a[mt][2] = cvt_tf32(asb[r * PA + ks + tig + 4]);
                a[mt][3] = cvt_tf32(asb[(r + 8) * PA + ks + tig + 4]);
            }
#pragma unroll
            for (int nt = 0; nt < 4; nt++) {
                int n = wn * 32 + nt * 8 + g;
                b[nt][0] = __float_as_uint(wsb[(ks + tig) * PB + n]);       // pre-cvt'd
                b[nt][1] = __float_as_uint(wsb[(ks + tig + 4) * PB + n]);
            }
#pragma unroll
            for (int mt = 0; mt < 2; mt++)
#pragma unroll
                for (int nt = 0; nt < 4; nt++) {
                    asm volatile(
                        "mma.sync.aligned.m16n8k8.row.col.f32.tf32.tf32.f32 "
                        "{%0,%1,%2,%3}, {%4,%5,%6,%7}, {%8,%9}, {%0,%1,%2,%3};"
                        : "+f"(c[mt][nt][0]), "+f"(c[mt][nt][1]),
                          "+f"(c[mt][nt][2]), "+f"(c[mt][nt][3])
                        : "r"(a[mt][0]), "r"(a[mt][1]), "r"(a[mt][2]), "r"(a[mt][3]),
                          "r"(b[nt][0]), "r"(b[nt][1]));
                }
        }
        __syncthreads();
    }

    // --- epilogue: hn = acc * dinv[row]  (pre-scaled)
#pragma unroll
    for (int mt = 0; mt < 2; mt++) {
        int rbase = m0 + wm * 32 + mt * 16 + g;
#pragma unroll
        for (int half = 0; half < 2; half++) {
            int row = rbase + half * 8;
            if (row < M) {
                float s = __ldg(&dinv[row]);
#pragma unroll
                for (int nt = 0; nt < 4; nt++) {
                    float2 v;
                    v.x = c[mt][nt][half * 2 + 0] * s;
                    v.y = c[mt][nt][half * 2 + 1] * s;
                    *(float2*)(hn + (size_t)row * 64 + wn * 32 + nt * 8 + 2 * tig) = v;
                }
            }
        }
    }
}

// ---------------------------------------------------------------------------
// Fused aggregate (warp per node, hn pre-scaled, float2 lanes):
//   out[i] = act(dinv[i] * (hn[i] + sum_e hn[col[e]]) + b)
// ONE LDG.64 per edge per warp.
// ---------------------------------------------------------------------------
template <bool RELU>
__global__ void __launch_bounds__(256)
k_agg(const int* __restrict__ rowptr, const int* __restrict__ col,
      const float2* __restrict__ hn2, const float* __restrict__ dinv,
      const float2* __restrict__ bias2, float2* __restrict__ out2, int n) {
    int w = (blockIdx.x * blockDim.x + threadIdx.x) >> 5;
    int lane = threadIdx.x & 31;
    if (w >= n) return;

    float2 acc = __ldg(&hn2[(size_t)w * 32 + lane]);   // self-loop (pre-scaled)

    int beg = __ldg(&rowptr[w]);
    int end = __ldg(&rowptr[w + 1]);

    for (int e0 = beg; e0 < end; e0 += 16) {
        int idx = e0 + (lane & 15);
        int cs = (idx < end) ? __ldg(&col[idx]) : -1;
#pragma unroll
        for (int j = 0; j < 16; j++) {
            int s = __shfl_sync(0xffffffffu, cs, j);
            if (s >= 0) {
                float2 v = __ldg(&hn2[(size_t)s * 32 + lane]);
                acc.x += v.x;
                acc.y += v.y;
            }
        }
    }

    float di = __ldg(&dinv[w]);
    float2 b = __ldg(&bias2[lane]);
    float2 v;
    v.x = di * acc.x + b.x;
    v.y = di * acc.y + b.y;
    if (RELU) { v.x = fmaxf(v.x, 0.0f); v.y = fmaxf(v.y, 0.0f); }
    out2[(size_t)w * 32 + lane] = v;
}

// ---------------------------------------------------------------------------
// Launch (GEMM1 at slot #4 for profiling consistency)
// ---------------------------------------------------------------------------
extern "C" void kernel_launch(void* const* d_in, const int* in_sizes, int n_in,
                              void* d_out, int out_size) {
    const float* x  = (const float*)d_in[0];
    const int*   ei = (const int*)d_in[1];
    const float* W1 = (const float*)d_in[2];
    const float* b1 = (const float*)d_in[3];
    const float* W2 = (const float*)d_in[4];
    const float* b2 = (const float*)d_in[5];

    const int E = in_sizes[1] / 2;
    const int M = out_size / HID;
    const int* src = ei;
    const int* dst = ei + E;

    float *dinv, *bufA, *bufB, *w1t, *w2t;
    int *cnt, *rowptr, *cursor, *col, *bsum;
    cudaGetSymbolAddress((void**)&dinv,   g_dinv);
    cudaGetSymbolAddress((void**)&cnt,    g_cnt);
    cudaGetSymbolAddress((void**)&rowptr, g_rowptr);
    cudaGetSymbolAddress((void**)&cursor, g_cursor);
    cudaGetSymbolAddress((void**)&col,    g_col);
    cudaGetSymbolAddress((void**)&bsum,   g_bsum);
    cudaGetSymbolAddress((void**)&w1t,    g_w1t);
    cudaGetSymbolAddress((void**)&w2t,    g_w2t);
    cudaGetSymbolAddress((void**)&bufA,   g_bufA);
    cudaGetSymbolAddress((void**)&bufB,   g_bufB);
    float* out = (float*)d_out;

    const int gblk = (M + BM - 1) / BM;
    const int ablk = (M * 32 + 255) / 256;
    const int nb   = (M + SCAN_B - 1) / SCAN_B;

    // 1-3. degree count, then dinv + W preconvert
    k_zero<<<(M + 255) / 256, 256>>>(cnt, M);
    k_count<<<592, 256>>>(dst, cnt, E);
    k_prep<<<(M + 255) / 256, 256>>>(cnt, dinv, W1, W2, w1t, w2t, M);

    // 4. GEMM1 (slot #4): hn1 = (x@W1)*dinv -> bufA
    k_gemm<IN_DIM><<<gblk, 128>>>(x, w1t, dinv, bufA, M);

    // 5-7. CSR scan + fill
    k_s1<<<nb, SCAN_B>>>(cnt, bsum, M);
    k_s3<<<nb, SCAN_B>>>(cnt, bsum, rowptr, cursor, nb, M);
    k_fill<<<592, 256>>>(src, dst, cursor, col, E);

    // 8. agg1 (+bias1, ReLU) -> bufB
    k_agg<true><<<ablk, 256>>>(rowptr, col, (const float2*)bufA, dinv,
                               (const float2*)b1, (float2*)bufB, M);

    // 9-10. GEMM2 -> bufA (pre-scaled) ; agg2 (+bias2) -> out
    k_gemm<HID><<<gblk, 128>>>(bufB, w2t, dinv, bufA, M);
    k_agg<false><<<ablk, 256>>>(rowptr, col, (const float2*)bufA, dinv,
                                (const float2*)b2, (float2*)out, M);
}